// round 2
// baseline (speedup 1.0000x reference)
#include <cuda_runtime.h>
#include <math.h>

#define N_NODES   100000
#define N_EDGES   3200000
#define NODE_DIM  128
#define HID       16
#define N_GRAPHS  256
#define MRI_DIM   256
#define COG_DIM   64
#define CLIN_DIM  32
#define GEN_DIM   512

// ---------------- device scratch (static allocation is allowed) -------------
__device__ float g_xw[(size_t)N_NODES * HID];    // x @ gcn_W
__device__ float g_agg[(size_t)N_NODES * HID];   // scatter-add accumulator -> relu(g)
__device__ float g_dinv[N_NODES];                // degree, then rsqrt(degree)

// ---------------- init: zero agg, deg = 1 (self loop) -----------------------
__global__ void k_init() {
    int i = blockIdx.x * blockDim.x + threadIdx.x;
    if (i < N_NODES * HID) g_agg[i] = 0.0f;
    if (i < N_NODES)       g_dinv[i] = 1.0f;
}

// ---------------- xw = x @ W  (warp handles 4 rows, 8 lanes per row) --------
__global__ __launch_bounds__(256) void k_xw(const float* __restrict__ x,
                                            const float* __restrict__ W) {
    // smem: sW4[c*32 + f] = {W[4f+0][c], W[4f+1][c], W[4f+2][c], W[4f+3][c]}
    __shared__ float4 sW4[16 * 32];
    for (int q = threadIdx.x; q < 512; q += 256) {
        int c = q >> 5, f = q & 31;
        sW4[q] = make_float4(W[(4 * f + 0) * HID + c], W[(4 * f + 1) * HID + c],
                             W[(4 * f + 2) * HID + c], W[(4 * f + 3) * HID + c]);
    }
    __syncthreads();

    int warp = (blockIdx.x * blockDim.x + threadIdx.x) >> 5;
    int lane = threadIdx.x & 31;
    int row  = warp * 4 + (lane >> 3);        // 25000 warps * 4 rows = 100000
    int sub  = lane & 7;
    if (row >= N_NODES) return;

    const float4* xr = reinterpret_cast<const float4*>(x + (size_t)row * NODE_DIM);
    float acc[16];
#pragma unroll
    for (int c = 0; c < 16; c++) acc[c] = 0.0f;

#pragma unroll
    for (int i = 0; i < 4; i++) {
        float4 xv = __ldg(&xr[sub * 4 + i]);
        int f = sub * 4 + i;
#pragma unroll
        for (int c = 0; c < 16; c++) {
            float4 wv = sW4[c * 32 + f];
            acc[c] += xv.x * wv.x + xv.y * wv.y + xv.z * wv.z + xv.w * wv.w;
        }
    }
    // reduce across the 8 lanes of this row
#pragma unroll
    for (int off = 4; off; off >>= 1)
#pragma unroll
        for (int c = 0; c < 16; c++)
            acc[c] += __shfl_xor_sync(0xffffffffu, acc[c], off);

    if (sub == 0) {
        float4* o = reinterpret_cast<float4*>(&g_xw[(size_t)row * HID]);
        o[0] = make_float4(acc[0], acc[1], acc[2], acc[3]);
        o[1] = make_float4(acc[4], acc[5], acc[6], acc[7]);
        o[2] = make_float4(acc[8], acc[9], acc[10], acc[11]);
        o[3] = make_float4(acc[12], acc[13], acc[14], acc[15]);
    }
}

// ---------------- degree: scatter-add 1 at dst -------------------------------
__global__ __launch_bounds__(256) void k_deg(const int* __restrict__ ei) {
    int e = blockIdx.x * blockDim.x + threadIdx.x;
    if (e >= N_EDGES) return;
    int d = __ldg(&ei[N_EDGES + e]);
    atomicAdd(&g_dinv[d], 1.0f);
}

// ---------------- deg -> rsqrt(deg) (deg >= 1 always) ------------------------
__global__ __launch_bounds__(256) void k_rsqrt() {
    int i = blockIdx.x * blockDim.x + threadIdx.x;
    if (i < N_NODES) g_dinv[i] = rsqrtf(g_dinv[i]);
}

// ---------------- edge messages: agg[dst] += xw[src] * dinv[s]*dinv[d] -------
__global__ __launch_bounds__(256) void k_msg(const int* __restrict__ ei) {
    int t = blockIdx.x * blockDim.x + threadIdx.x;
    int e = t >> 2;
    if (e >= N_EDGES) return;
    int part = t & 3;
    int s = __ldg(&ei[e]);
    int d = __ldg(&ei[N_EDGES + e]);
    float w = __ldg(&g_dinv[s]) * __ldg(&g_dinv[d]);
    float4 v = *reinterpret_cast<const float4*>(&g_xw[(size_t)s * HID + part * 4]);
    float* dst = &g_agg[(size_t)d * HID + part * 4];
    asm volatile("red.global.add.v4.f32 [%0], {%1,%2,%3,%4};"
                 :: "l"(dst), "f"(v.x * w), "f"(v.y * w), "f"(v.z * w), "f"(v.w * w)
                 : "memory");
}

// ---------------- node finalize: agg = relu(agg + xw*dinv^2 + b) -------------
__global__ __launch_bounds__(256) void k_node(const float* __restrict__ b) {
    int i = blockIdx.x * blockDim.x + threadIdx.x;
    if (i >= N_NODES) return;
    float di = g_dinv[i];
    float w  = di * di;
    const float4* xr = reinterpret_cast<const float4*>(&g_xw[(size_t)i * HID]);
    float4* ar = reinterpret_cast<float4*>(&g_agg[(size_t)i * HID]);
    const float4* bb = reinterpret_cast<const float4*>(b);
#pragma unroll
    for (int j = 0; j < 4; j++) {
        float4 a = ar[j], xv = xr[j], bv = __ldg(&bb[j]);
        a.x = fmaxf(a.x + xv.x * w + bv.x, 0.0f);
        a.y = fmaxf(a.y + xv.y * w + bv.y, 0.0f);
        a.z = fmaxf(a.z + xv.z * w + bv.z, 0.0f);
        a.w = fmaxf(a.w + xv.w * w + bv.w, 0.0f);
        ar[j] = a;
    }
}

// ---------------- head: pool (sorted batch -> binary search), modality FCs,
//                  classifier, log_softmax. One block per graph. -------------
__global__ __launch_bounds__(128) void k_head(
    const int* __restrict__ batch,
    const float* __restrict__ mri,  const float* __restrict__ cog,
    const float* __restrict__ clin, const float* __restrict__ gen,
    const float* __restrict__ mri_W, const float* __restrict__ mri_b,
    const float* __restrict__ cog_W, const float* __restrict__ cog_b,
    const float* __restrict__ clin_W, const float* __restrict__ clin_b,
    const float* __restrict__ gen_W, const float* __restrict__ gen_b,
    const float* __restrict__ W1, const float* __restrict__ b1,
    const float* __restrict__ W2, const float* __restrict__ b2,
    float* __restrict__ out)
{
    int g = blockIdx.x;
    int t = threadIdx.x;  // 128 threads

    __shared__ int s_bounds[2];
    if (t < 2) {
        int target = g + t;
        int lo = 0, hi = N_NODES;
        while (lo < hi) {
            int mid = (lo + hi) >> 1;
            if (batch[mid] < target) lo = mid + 1; else hi = mid;
        }
        s_bounds[t] = lo;
    }
    __syncthreads();
    int start = s_bounds[0], end = s_bounds[1];

    // v[0..15]  : pooled sum of node features
    // v[16..31] : modality partials (mri4, cog4, clin4, gen4)
    float v[32];
#pragma unroll
    for (int j = 0; j < 32; j++) v[j] = 0.0f;

    for (int n = start + t; n < end; n += 128) {
        const float4* r = reinterpret_cast<const float4*>(&g_agg[(size_t)n * HID]);
        float4 a = r[0], b_ = r[1], c_ = r[2], d_ = r[3];
        v[0] += a.x;  v[1] += a.y;  v[2] += a.z;  v[3] += a.w;
        v[4] += b_.x; v[5] += b_.y; v[6] += b_.z; v[7] += b_.w;
        v[8] += c_.x; v[9] += c_.y; v[10]+= c_.z; v[11]+= c_.w;
        v[12]+= d_.x; v[13]+= d_.y; v[14]+= d_.z; v[15]+= d_.w;
    }
    {
        const float* row = mri + (size_t)g * MRI_DIM;
        for (int k = t; k < MRI_DIM; k += 128) {
            float x = __ldg(&row[k]);
#pragma unroll
            for (int c = 0; c < 4; c++) v[16 + c] += x * __ldg(&mri_W[k * 4 + c]);
        }
    }
    if (t < COG_DIM) {
        const float* row = cog + (size_t)g * COG_DIM;
        float x = __ldg(&row[t]);
#pragma unroll
        for (int c = 0; c < 4; c++) v[20 + c] += x * __ldg(&cog_W[t * 4 + c]);
    }
    if (t < CLIN_DIM) {
        const float* row = clin + (size_t)g * CLIN_DIM;
        float x = __ldg(&row[t]);
#pragma unroll
        for (int c = 0; c < 4; c++) v[24 + c] += x * __ldg(&clin_W[t * 4 + c]);
    }
    {
        const float* row = gen + (size_t)g * GEN_DIM;
        for (int k = t; k < GEN_DIM; k += 128) {
            float x = __ldg(&row[k]);
#pragma unroll
            for (int c = 0; c < 4; c++) v[28 + c] += x * __ldg(&gen_W[k * 4 + c]);
        }
    }

    // block reduction of 32 values: warp shfl, then cross-warp via smem
#pragma unroll
    for (int off = 16; off; off >>= 1)
#pragma unroll
        for (int j = 0; j < 32; j++)
            v[j] += __shfl_xor_sync(0xffffffffu, v[j], off);

    __shared__ float s_red[4][32];
    int warp = t >> 5, lane = t & 31;
    if (lane == 0)
#pragma unroll
        for (int j = 0; j < 32; j++) s_red[warp][j] = v[j];
    __syncthreads();

    __shared__ float s_comb[32];
    if (t < 32) {
        float val = s_red[0][t] + s_red[1][t] + s_red[2][t] + s_red[3][t];
        if (t < 16) {
            float cnt = fmaxf((float)(end - start), 1.0f);
            s_comb[t] = val / cnt;
        } else {
            int c = (t - 16) & 3;
            int m = (t - 16) >> 2;
            float bias = (m == 0) ? __ldg(&mri_b[c]) :
                         (m == 1) ? __ldg(&cog_b[c]) :
                         (m == 2) ? __ldg(&clin_b[c]) : __ldg(&gen_b[c]);
            s_comb[t] = fmaxf(val + bias, 0.0f);
        }
    }
    __syncthreads();

    __shared__ float s_h[16];
    if (t < 16) {
        float h = __ldg(&b1[t]);
#pragma unroll
        for (int i = 0; i < 32; i++) h += s_comb[i] * __ldg(&W1[i * 16 + t]);
        s_h[t] = fmaxf(h, 0.0f);
    }
    __syncthreads();

    __shared__ float s_lg[3];
    if (t < 3) {
        float lg = __ldg(&b2[t]);
#pragma unroll
        for (int j = 0; j < 16; j++) lg += s_h[j] * __ldg(&W2[j * 3 + t]);
        s_lg[t] = lg;
    }
    __syncthreads();

    if (t == 0) {
        float m = fmaxf(fmaxf(s_lg[0], s_lg[1]), s_lg[2]);
        float se = expf(s_lg[0] - m) + expf(s_lg[1] - m) + expf(s_lg[2] - m);
        float lse = m + logf(se);
        out[g * 3 + 0] = s_lg[0] - lse;
        out[g * 3 + 1] = s_lg[1] - lse;
        out[g * 3 + 2] = s_lg[2] - lse;
    }
}

// -----------------------------------------------------------------------------
extern "C" void kernel_launch(void* const* d_in, const int* in_sizes, int n_in,
                              void* d_out, int out_size) {
    const float* x      = (const float*)d_in[0];
    const int*   ei     = (const int*)d_in[1];     // int32 (JAX x64 disabled)
    const int*   batch  = (const int*)d_in[2];     // int32
    const float* mri    = (const float*)d_in[3];
    const float* cog    = (const float*)d_in[4];
    const float* clin   = (const float*)d_in[5];
    const float* gen    = (const float*)d_in[6];
    const float* gcn_W  = (const float*)d_in[7];
    const float* gcn_b  = (const float*)d_in[8];
    const float* mri_W  = (const float*)d_in[9];
    const float* mri_b  = (const float*)d_in[10];
    const float* cog_W  = (const float*)d_in[11];
    const float* cog_b  = (const float*)d_in[12];
    const float* clin_W = (const float*)d_in[13];
    const float* clin_b = (const float*)d_in[14];
    const float* gen_W  = (const float*)d_in[15];
    const float* gen_b  = (const float*)d_in[16];
    const float* W1     = (const float*)d_in[17];
    const float* b1     = (const float*)d_in[18];
    const float* W2     = (const float*)d_in[19];
    const float* b2     = (const float*)d_in[20];
    float* out = (float*)d_out;

    k_init<<<(N_NODES * HID + 255) / 256, 256>>>();
    k_xw<<<(N_NODES + 31) / 32, 256>>>(x, gcn_W);        // 32 rows per block
    k_deg<<<(N_EDGES + 255) / 256, 256>>>(ei);
    k_rsqrt<<<(N_NODES + 255) / 256, 256>>>();
    k_msg<<<(N_EDGES * 4 + 255) / 256, 256>>>(ei);
    k_node<<<(N_NODES + 255) / 256, 256>>>(gcn_b);
    k_head<<<N_GRAPHS, 128>>>(batch, mri, cog, clin, gen,
                              mri_W, mri_b, cog_W, cog_b, clin_W, clin_b,
                              gen_W, gen_b, W1, b1, W2, b2, out);
}

// round 3
// speedup vs baseline: 1.0280x; 1.0280x over previous
#include <cuda_runtime.h>
#include <math.h>

#define N_NODES   100000
#define N_EDGES   3200000
#define NODE_DIM  128
#define HID       16
#define N_GRAPHS  256
#define MRI_DIM   256
#define COG_DIM   64
#define CLIN_DIM  32
#define GEN_DIM   512

#define SCAN_B 1024
#define NB ((N_NODES + SCAN_B - 1) / SCAN_B)   // 98

// ---------------- device scratch -------------------------------------------
__device__ float g_xw[(size_t)N_NODES * HID];    // x @ gcn_W
__device__ float g_agg[(size_t)N_NODES * HID];   // relu(gcn output)
__device__ float g_dinv[N_NODES];                // rsqrt(degree incl self loop)
__device__ int   g_deg[N_NODES];                 // edge in-degree (no self loop)
__device__ int   g_start[N_NODES];               // exclusive offsets
__device__ int   g_cursor[N_NODES];              // mutable cursor for scatter
__device__ int   g_bsum[NB];
__device__ int   g_srcs[N_EDGES];                // src ids sorted by dst

// ---------------- zero degree histogram -------------------------------------
__global__ void k_zero() {
    int i = blockIdx.x * blockDim.x + threadIdx.x;
    if (i < N_NODES) g_deg[i] = 0;
}

// ---------------- xw = x @ W  (warp handles 4 rows, 8 lanes per row) --------
__global__ __launch_bounds__(256) void k_xw(const float* __restrict__ x,
                                            const float* __restrict__ W) {
    __shared__ float4 sW4[16 * 32];
    for (int q = threadIdx.x; q < 512; q += 256) {
        int c = q >> 5, f = q & 31;
        sW4[q] = make_float4(W[(4 * f + 0) * HID + c], W[(4 * f + 1) * HID + c],
                             W[(4 * f + 2) * HID + c], W[(4 * f + 3) * HID + c]);
    }
    __syncthreads();

    int warp = (blockIdx.x * blockDim.x + threadIdx.x) >> 5;
    int lane = threadIdx.x & 31;
    int row  = warp * 4 + (lane >> 3);
    int sub  = lane & 7;
    if (row >= N_NODES) return;

    const float4* xr = reinterpret_cast<const float4*>(x + (size_t)row * NODE_DIM);
    float acc[16];
#pragma unroll
    for (int c = 0; c < 16; c++) acc[c] = 0.0f;

#pragma unroll
    for (int i = 0; i < 4; i++) {
        float4 xv = __ldg(&xr[sub * 4 + i]);
        int f = sub * 4 + i;
#pragma unroll
        for (int c = 0; c < 16; c++) {
            float4 wv = sW4[c * 32 + f];
            acc[c] += xv.x * wv.x + xv.y * wv.y + xv.z * wv.z + xv.w * wv.w;
        }
    }
#pragma unroll
    for (int off = 4; off; off >>= 1)
#pragma unroll
        for (int c = 0; c < 16; c++)
            acc[c] += __shfl_xor_sync(0xffffffffu, acc[c], off);

    if (sub == 0) {
        float4* o = reinterpret_cast<float4*>(&g_xw[(size_t)row * HID]);
        o[0] = make_float4(acc[0], acc[1], acc[2], acc[3]);
        o[1] = make_float4(acc[4], acc[5], acc[6], acc[7]);
        o[2] = make_float4(acc[8], acc[9], acc[10], acc[11]);
        o[3] = make_float4(acc[12], acc[13], acc[14], acc[15]);
    }
}

// ---------------- degree histogram -------------------------------------------
__global__ __launch_bounds__(256) void k_hist(const int* __restrict__ ei) {
    int e = blockIdx.x * blockDim.x + threadIdx.x;
    if (e >= N_EDGES) return;
    atomicAdd(&g_deg[__ldg(&ei[N_EDGES + e])], 1);
}

// ---------------- prefix scan (3 kernels) ------------------------------------
__global__ __launch_bounds__(SCAN_B) void k_scan1() {
    __shared__ int s[SCAN_B];
    int i = blockIdx.x * SCAN_B + threadIdx.x;
    int v = (i < N_NODES) ? g_deg[i] : 0;
    s[threadIdx.x] = v;
    __syncthreads();
#pragma unroll
    for (int off = 1; off < SCAN_B; off <<= 1) {
        int t = (threadIdx.x >= off) ? s[threadIdx.x - off] : 0;
        __syncthreads();
        s[threadIdx.x] += t;
        __syncthreads();
    }
    if (i < N_NODES) g_start[i] = s[threadIdx.x];        // inclusive for now
    if (threadIdx.x == SCAN_B - 1) g_bsum[blockIdx.x] = s[SCAN_B - 1];
}

__global__ __launch_bounds__(128) void k_scan2() {
    __shared__ int s[128];
    int t = threadIdx.x;
    s[t] = (t < NB) ? g_bsum[t] : 0;
    __syncthreads();
#pragma unroll
    for (int off = 1; off < 128; off <<= 1) {
        int v = (t >= off) ? s[t - off] : 0;
        __syncthreads();
        s[t] += v;
        __syncthreads();
    }
    if (t < NB) g_bsum[t] = s[t];                        // inclusive block sums
}

__global__ __launch_bounds__(256) void k_scan3() {
    int i = blockIdx.x * blockDim.x + threadIdx.x;
    if (i >= N_NODES) return;
    int bi = i / SCAN_B;
    int deg = g_deg[i];
    int incl = g_start[i] + (bi > 0 ? g_bsum[bi - 1] : 0);
    int excl = incl - deg;
    g_start[i]  = excl;
    g_cursor[i] = excl;
    g_dinv[i]   = rsqrtf((float)(deg + 1));              // +1 = self loop
}

// ---------------- scatter: bucket src ids by dst ------------------------------
__global__ __launch_bounds__(256) void k_scatter(const int* __restrict__ ei) {
    int e = blockIdx.x * blockDim.x + threadIdx.x;
    if (e >= N_EDGES) return;
    int s = __ldg(&ei[e]);
    int d = __ldg(&ei[N_EDGES + e]);
    int pos = atomicAdd(&g_cursor[d], 1);
    g_srcs[pos] = s;
}

// ---------------- segmented gather-reduce + finalize (warp per node) ----------
// out[d] = relu( dinv[d]*( sum_e dinv[src_e]*xw[src_e] + dinv[d]*xw[d] ) + b )
__global__ __launch_bounds__(256) void k_agg(const float* __restrict__ b) {
    int warp = (blockIdx.x * blockDim.x + threadIdx.x) >> 5;
    if (warp >= N_NODES) return;
    int lane = threadIdx.x & 31;
    int sub  = lane >> 2;          // edge slot 0..7
    int part = lane & 3;           // float4 quarter

    int start = g_start[warp];
    int end   = start + g_deg[warp];

    const float4* xw4 = reinterpret_cast<const float4*>(g_xw);
    float4 acc = make_float4(0.f, 0.f, 0.f, 0.f);
    for (int e = start + sub; e < end; e += 8) {
        int s = g_srcs[e];
        float wt = g_dinv[s];
        float4 v = __ldg(&xw4[(size_t)s * 4 + part]);
        acc.x += v.x * wt; acc.y += v.y * wt;
        acc.z += v.z * wt; acc.w += v.w * wt;
    }
#pragma unroll
    for (int off = 4; off <= 16; off <<= 1) {
        acc.x += __shfl_xor_sync(0xffffffffu, acc.x, off);
        acc.y += __shfl_xor_sync(0xffffffffu, acc.y, off);
        acc.z += __shfl_xor_sync(0xffffffffu, acc.z, off);
        acc.w += __shfl_xor_sync(0xffffffffu, acc.w, off);
    }
    if (lane < 4) {
        float di = g_dinv[warp];
        float4 self = xw4[(size_t)warp * 4 + lane];
        float4 bv = __ldg(&reinterpret_cast<const float4*>(b)[lane]);
        float4 o;
        o.x = fmaxf((acc.x + self.x * di) * di + bv.x, 0.0f);
        o.y = fmaxf((acc.y + self.y * di) * di + bv.y, 0.0f);
        o.z = fmaxf((acc.z + self.z * di) * di + bv.z, 0.0f);
        o.w = fmaxf((acc.w + self.w * di) * di + bv.w, 0.0f);
        reinterpret_cast<float4*>(g_agg)[(size_t)warp * 4 + lane] = o;
    }
}

// ---------------- head: pool + modality FCs + classifier + log_softmax -------
__global__ __launch_bounds__(128) void k_head(
    const int* __restrict__ batch,
    const float* __restrict__ mri,  const float* __restrict__ cog,
    const float* __restrict__ clin, const float* __restrict__ gen,
    const float* __restrict__ mri_W, const float* __restrict__ mri_b,
    const float* __restrict__ cog_W, const float* __restrict__ cog_b,
    const float* __restrict__ clin_W, const float* __restrict__ clin_b,
    const float* __restrict__ gen_W, const float* __restrict__ gen_b,
    const float* __restrict__ W1, const float* __restrict__ b1,
    const float* __restrict__ W2, const float* __restrict__ b2,
    float* __restrict__ out)
{
    int g = blockIdx.x;
    int t = threadIdx.x;

    __shared__ int s_bounds[2];
    if (t < 2) {
        int target = g + t;
        int lo = 0, hi = N_NODES;
        while (lo < hi) {
            int mid = (lo + hi) >> 1;
            if (batch[mid] < target) lo = mid + 1; else hi = mid;
        }
        s_bounds[t] = lo;
    }
    __syncthreads();
    int start = s_bounds[0], end = s_bounds[1];

    float v[32];
#pragma unroll
    for (int j = 0; j < 32; j++) v[j] = 0.0f;

    for (int n = start + t; n < end; n += 128) {
        const float4* r = reinterpret_cast<const float4*>(&g_agg[(size_t)n * HID]);
        float4 a = r[0], b_ = r[1], c_ = r[2], d_ = r[3];
        v[0] += a.x;  v[1] += a.y;  v[2] += a.z;  v[3] += a.w;
        v[4] += b_.x; v[5] += b_.y; v[6] += b_.z; v[7] += b_.w;
        v[8] += c_.x; v[9] += c_.y; v[10]+= c_.z; v[11]+= c_.w;
        v[12]+= d_.x; v[13]+= d_.y; v[14]+= d_.z; v[15]+= d_.w;
    }
    {
        const float* row = mri + (size_t)g * MRI_DIM;
        for (int k = t; k < MRI_DIM; k += 128) {
            float x = __ldg(&row[k]);
#pragma unroll
            for (int c = 0; c < 4; c++) v[16 + c] += x * __ldg(&mri_W[k * 4 + c]);
        }
    }
    if (t < COG_DIM) {
        float x = __ldg(&cog[(size_t)g * COG_DIM + t]);
#pragma unroll
        for (int c = 0; c < 4; c++) v[20 + c] += x * __ldg(&cog_W[t * 4 + c]);
    }
    if (t < CLIN_DIM) {
        float x = __ldg(&clin[(size_t)g * CLIN_DIM + t]);
#pragma unroll
        for (int c = 0; c < 4; c++) v[24 + c] += x * __ldg(&clin_W[t * 4 + c]);
    }
    {
        const float* row = gen + (size_t)g * GEN_DIM;
        for (int k = t; k < GEN_DIM; k += 128) {
            float x = __ldg(&row[k]);
#pragma unroll
            for (int c = 0; c < 4; c++) v[28 + c] += x * __ldg(&gen_W[k * 4 + c]);
        }
    }

#pragma unroll
    for (int off = 16; off; off >>= 1)
#pragma unroll
        for (int j = 0; j < 32; j++)
            v[j] += __shfl_xor_sync(0xffffffffu, v[j], off);

    __shared__ float s_red[4][32];
    int warp = t >> 5, lane = t & 31;
    if (lane == 0)
#pragma unroll
        for (int j = 0; j < 32; j++) s_red[warp][j] = v[j];
    __syncthreads();

    __shared__ float s_comb[32];
    if (t < 32) {
        float val = s_red[0][t] + s_red[1][t] + s_red[2][t] + s_red[3][t];
        if (t < 16) {
            float cnt = fmaxf((float)(end - start), 1.0f);
            s_comb[t] = val / cnt;
        } else {
            int c = (t - 16) & 3;
            int m = (t - 16) >> 2;
            float bias = (m == 0) ? __ldg(&mri_b[c]) :
                         (m == 1) ? __ldg(&cog_b[c]) :
                         (m == 2) ? __ldg(&clin_b[c]) : __ldg(&gen_b[c]);
            s_comb[t] = fmaxf(val + bias, 0.0f);
        }
    }
    __syncthreads();

    __shared__ float s_h[16];
    if (t < 16) {
        float h = __ldg(&b1[t]);
#pragma unroll
        for (int i = 0; i < 32; i++) h += s_comb[i] * __ldg(&W1[i * 16 + t]);
        s_h[t] = fmaxf(h, 0.0f);
    }
    __syncthreads();

    __shared__ float s_lg[3];
    if (t < 3) {
        float lg = __ldg(&b2[t]);
#pragma unroll
        for (int j = 0; j < 16; j++) lg += s_h[j] * __ldg(&W2[j * 3 + t]);
        s_lg[t] = lg;
    }
    __syncthreads();

    if (t == 0) {
        float m = fmaxf(fmaxf(s_lg[0], s_lg[1]), s_lg[2]);
        float se = expf(s_lg[0] - m) + expf(s_lg[1] - m) + expf(s_lg[2] - m);
        float lse = m + logf(se);
        out[g * 3 + 0] = s_lg[0] - lse;
        out[g * 3 + 1] = s_lg[1] - lse;
        out[g * 3 + 2] = s_lg[2] - lse;
    }
}

// -----------------------------------------------------------------------------
extern "C" void kernel_launch(void* const* d_in, const int* in_sizes, int n_in,
                              void* d_out, int out_size) {
    const float* x      = (const float*)d_in[0];
    const int*   ei     = (const int*)d_in[1];
    const int*   batch  = (const int*)d_in[2];
    const float* mri    = (const float*)d_in[3];
    const float* cog    = (const float*)d_in[4];
    const float* clin   = (const float*)d_in[5];
    const float* gen    = (const float*)d_in[6];
    const float* gcn_W  = (const float*)d_in[7];
    const float* gcn_b  = (const float*)d_in[8];
    const float* mri_W  = (const float*)d_in[9];
    const float* mri_b  = (const float*)d_in[10];
    const float* cog_W  = (const float*)d_in[11];
    const float* cog_b  = (const float*)d_in[12];
    const float* clin_W = (const float*)d_in[13];
    const float* clin_b = (const float*)d_in[14];
    const float* gen_W  = (const float*)d_in[15];
    const float* gen_b  = (const float*)d_in[16];
    const float* W1     = (const float*)d_in[17];
    const float* b1     = (const float*)d_in[18];
    const float* W2     = (const float*)d_in[19];
    const float* b2     = (const float*)d_in[20];
    float* out = (float*)d_out;

    k_zero<<<(N_NODES + 255) / 256, 256>>>();
    k_xw<<<(N_NODES + 31) / 32, 256>>>(x, gcn_W);
    k_hist<<<(N_EDGES + 255) / 256, 256>>>(ei);
    k_scan1<<<NB, SCAN_B>>>();
    k_scan2<<<1, 128>>>();
    k_scan3<<<(N_NODES + 255) / 256, 256>>>();
    k_scatter<<<(N_EDGES + 255) / 256, 256>>>(ei);
    k_agg<<<(N_NODES * 32 + 255) / 256, 256>>>(gcn_b);
    k_head<<<N_GRAPHS, 128>>>(batch, mri, cog, clin, gen,
                              mri_W, mri_b, cog_W, cog_b, clin_W, clin_b,
                              gen_W, gen_b, W1, b1, W2, b2, out);
}